// round 3
// baseline (speedup 1.0000x reference)
#include <cuda_runtime.h>

// FSQ: x (64, 32768, 4) fp32. N = 2097152 tokens, LEVELS = [8,5,5,5].
// out fp32 planes: out[d*N + n] = q_d, out[4*N + n] = code.
// Persistent one-wave grid (148 SMs x 8 blocks), grid-stride over 4-token groups.
// Quantizer: (tanh(x)+1)/2 = rcp(1+ex2(-2x*log2e)); idx = rint(r*(L-1)).

#define FSQ_N (64 * 32768)
#define NGROUPS (FSQ_N / 4)          // 524288 four-token groups
#define NBLOCKS (148 * 8)            // one full wave
#define NTHREADS 256

__device__ __forceinline__ float fast_ex2(float x) {
    float y;
    asm("ex2.approx.f32 %0, %1;" : "=f"(y) : "f"(x));
    return y;
}
__device__ __forceinline__ float fast_rcp(float x) {
    float y;
    asm("rcp.approx.f32 %0, %1;" : "=f"(y) : "f"(x));
    return y;
}

__device__ __forceinline__ int quant(float x, float scale, float step, float& q) {
    const float NEG2LOG2E = -2.8853900817779268f;  // -2*log2(e)
    float e = fast_ex2(x * NEG2LOG2E);             // e^(-2x)
    float r = fast_rcp(1.0f + e);                  // (tanh(x)+1)/2
    int idx = __float2int_rn(r * scale);
    q = (float)idx * step - 1.0f;
    return idx;
}

__device__ __forceinline__ void do_token(const float4& v, float& o0, float& o1,
                                         float& o2, float& o3, float& oc) {
    int i0 = quant(v.x, 7.0f, 2.0f / 7.0f, o0);
    int i1 = quant(v.y, 4.0f, 0.5f, o1);
    int i2 = quant(v.z, 4.0f, 0.5f, o2);
    int i3 = quant(v.w, 4.0f, 0.5f, o3);
    oc = (float)(i0 + 8 * i1 + 40 * i2 + 200 * i3);
}

__global__ __launch_bounds__(NTHREADS) void fsq_kernel(const float4* __restrict__ x4,
                                                       float4* __restrict__ out4) {
    const int stride = NBLOCKS * NTHREADS;
    const int PN4 = FSQ_N / 4;  // plane size in float4 units

    for (int g = blockIdx.x * NTHREADS + threadIdx.x; g < NGROUPS; g += stride) {
        float4 v0 = __ldcs(&x4[4 * g + 0]);
        float4 v1 = __ldcs(&x4[4 * g + 1]);
        float4 v2 = __ldcs(&x4[4 * g + 2]);
        float4 v3 = __ldcs(&x4[4 * g + 3]);

        float4 z0, z1, z2, z3, zc;
        do_token(v0, z0.x, z1.x, z2.x, z3.x, zc.x);
        do_token(v1, z0.y, z1.y, z2.y, z3.y, zc.y);
        do_token(v2, z0.z, z1.z, z2.z, z3.z, zc.z);
        do_token(v3, z0.w, z1.w, z2.w, z3.w, zc.w);

        __stcs(&out4[0 * PN4 + g], z0);
        __stcs(&out4[1 * PN4 + g], z1);
        __stcs(&out4[2 * PN4 + g], z2);
        __stcs(&out4[3 * PN4 + g], z3);
        __stcs(&out4[4 * PN4 + g], zc);
    }
}

extern "C" void kernel_launch(void* const* d_in, const int* in_sizes, int n_in,
                              void* d_out, int out_size) {
    const float4* x4 = (const float4*)d_in[0];
    float4* out4 = (float4*)d_out;
    fsq_kernel<<<NBLOCKS, NTHREADS>>>(x4, out4);
}